// round 1
// baseline (speedup 1.0000x reference)
#include <cuda_runtime.h>
#include <math.h>

// Problem constants
#define DIM   1024
#define NH    16
#define HD    64
#define SEQ   2048
#define BATCH 2
#define NTOK  (BATCH*SEQ)   // 4096
#define FFN   (4*DIM)       // 4096

// ---------------- scratch (static device globals; no allocs allowed) --------
__device__ float g_q[(size_t)NTOK*DIM];      // [b*NH+h][SEQ][HD]
__device__ float g_k[(size_t)NTOK*DIM];
__device__ float g_v[(size_t)NTOK*DIM];
__device__ float g_attn[(size_t)NTOK*DIM];   // [token][dim]
__device__ float g_x1[(size_t)NTOK*DIM];     // x + attn@wo
__device__ float g_hbuf[(size_t)NTOK*FFN];   // relu(x1@w1)

// ---------------- generic fp32 tiled GEMM: C = epi(A[M,K] @ B[K,N]) ---------
#define TBM 128
#define TBN 128
#define TBK 16

#define EPI_SCATTER 0   // write to per-head layout [(b*NH+h)*SEQ+s][HD]
#define EPI_RES     1   // C = res + acc
#define EPI_RELU    2   // C = max(acc, 0)

__global__ __launch_bounds__(256) void gemm_k(
    const float* __restrict__ A, const float* __restrict__ B,
    const float* __restrict__ res, float* __restrict__ C,
    int M, int N, int K, int epi)
{
    __shared__ float As[TBK][TBM + 4];   // [k][m] (transposed A tile)
    __shared__ float Bs[TBK][TBN + 4];   // [k][n]

    const int tid = threadIdx.x;
    const int tx  = tid & 15;
    const int ty  = tid >> 4;
    const int bm  = blockIdx.y * TBM;
    const int bn  = blockIdx.x * TBN;

    float acc[8][8];
#pragma unroll
    for (int i = 0; i < 8; i++)
#pragma unroll
        for (int j = 0; j < 8; j++) acc[i][j] = 0.f;

    for (int kt = 0; kt < K; kt += TBK) {
        // load A tile 128x16 (512 float4, 2 per thread), store transposed
#pragma unroll
        for (int i = 0; i < 2; i++) {
            int f  = tid + i * 256;
            int r  = f >> 2;
            int c4 = (f & 3) << 2;
            float4 va = *reinterpret_cast<const float4*>(
                &A[(size_t)(bm + r) * K + kt + c4]);
            As[c4 + 0][r] = va.x; As[c4 + 1][r] = va.y;
            As[c4 + 2][r] = va.z; As[c4 + 3][r] = va.w;
        }
        // load B tile 16x128 (512 float4, 2 per thread), natural layout
#pragma unroll
        for (int i = 0; i < 2; i++) {
            int f  = tid + i * 256;
            int r  = f >> 5;
            int c4 = (f & 31) << 2;
            float4 vb = *reinterpret_cast<const float4*>(
                &B[(size_t)(kt + r) * N + bn + c4]);
            *reinterpret_cast<float4*>(&Bs[r][c4]) = vb;
        }
        __syncthreads();

#pragma unroll
        for (int k = 0; k < TBK; k++) {
            float a[8], b[8];
            float4 a0 = *reinterpret_cast<const float4*>(&As[k][ty * 8]);
            float4 a1 = *reinterpret_cast<const float4*>(&As[k][ty * 8 + 4]);
            float4 b0 = *reinterpret_cast<const float4*>(&Bs[k][tx * 8]);
            float4 b1 = *reinterpret_cast<const float4*>(&Bs[k][tx * 8 + 4]);
            a[0]=a0.x; a[1]=a0.y; a[2]=a0.z; a[3]=a0.w;
            a[4]=a1.x; a[5]=a1.y; a[6]=a1.z; a[7]=a1.w;
            b[0]=b0.x; b[1]=b0.y; b[2]=b0.z; b[3]=b0.w;
            b[4]=b1.x; b[5]=b1.y; b[6]=b1.z; b[7]=b1.w;
#pragma unroll
            for (int i = 0; i < 8; i++)
#pragma unroll
                for (int j = 0; j < 8; j++)
                    acc[i][j] = fmaf(a[i], b[j], acc[i][j]);
        }
        __syncthreads();
    }

    // epilogue
#pragma unroll
    for (int i = 0; i < 8; i++) {
        int m = bm + ty * 8 + i;
#pragma unroll
        for (int j = 0; j < 8; j++) {
            int n = bn + tx * 8 + j;
            float vv = acc[i][j];
            if (epi == EPI_SCATTER) {
                int b_ = m >> 11;        // m / SEQ
                int s_ = m & (SEQ - 1);
                int h_ = n >> 6;         // n / HD
                int d_ = n & (HD - 1);
                C[(((size_t)(b_ * NH + h_)) * SEQ + s_) * HD + d_] = vv;
            } else if (epi == EPI_RES) {
                size_t idx = (size_t)m * N + n;
                C[idx] = res[idx] + vv;
            } else {
                C[(size_t)m * N + n] = fmaxf(vv, 0.f);
            }
        }
    }
}

// ---------------- fused flash attention (fp32, online softmax) --------------
// grid: (SEQ/FBQ, BATCH*NH), block: 256 threads (16x16)
#define FBQ 64
#define FBK 32

__global__ __launch_bounds__(256) void flash_k(
    const float* __restrict__ q, const float* __restrict__ k,
    const float* __restrict__ v, float* __restrict__ out)
{
    __shared__ float Qs[HD][FBQ + 1];    // [d][r], pre-scaled
    __shared__ float Kt[HD][FBK + 1];    // [d][c]
    __shared__ float Ps[FBK][FBQ + 1];   // [c][r]
    __shared__ float Vs[FBK][HD + 4];    // [c][d]

    const int tid = threadIdx.x;
    const int tx  = tid & 15;
    const int ty  = tid >> 4;
    const int bh  = blockIdx.y;
    const int q0  = blockIdx.x * FBQ;
    const float scale = 0.125f;          // 64^{-1/2}

    const float* qb = q + (size_t)bh * SEQ * HD;
    const float* kb = k + (size_t)bh * SEQ * HD;
    const float* vb = v + (size_t)bh * SEQ * HD;

    // load Q tile (64x64) transposed + scaled
#pragma unroll
    for (int i = 0; i < 4; i++) {
        int f  = tid + i * 256;          // 1024 float4 total
        int r  = f >> 4;
        int d4 = (f & 15) << 2;
        float4 t = *reinterpret_cast<const float4*>(
            &qb[(size_t)(q0 + r) * HD + d4]);
        Qs[d4 + 0][r] = t.x * scale; Qs[d4 + 1][r] = t.y * scale;
        Qs[d4 + 2][r] = t.z * scale; Qs[d4 + 3][r] = t.w * scale;
    }

    float mrow[4], lrow[4], o[4][4];
#pragma unroll
    for (int i = 0; i < 4; i++) {
        mrow[i] = -1e30f; lrow[i] = 0.f;
#pragma unroll
        for (int j = 0; j < 4; j++) o[i][j] = 0.f;
    }

    for (int c0 = 0; c0 < SEQ; c0 += FBK) {
        __syncthreads();   // previous iteration's Ps/Vs reads complete
        // load K tile (32x64) transposed + V tile (32x64) natural
#pragma unroll
        for (int i = 0; i < 2; i++) {
            int f  = tid + i * 256;      // 512 float4 total
            int c  = f >> 4;
            int d4 = (f & 15) << 2;
            float4 t = *reinterpret_cast<const float4*>(
                &kb[(size_t)(c0 + c) * HD + d4]);
            Kt[d4 + 0][c] = t.x; Kt[d4 + 1][c] = t.y;
            Kt[d4 + 2][c] = t.z; Kt[d4 + 3][c] = t.w;
            float4 tv = *reinterpret_cast<const float4*>(
                &vb[(size_t)(c0 + c) * HD + d4]);
            *reinterpret_cast<float4*>(&Vs[c][d4]) = tv;
        }
        __syncthreads();

        // S tile: rows ty*4.., cols tx*2..
        float s0[4], s1[4];
#pragma unroll
        for (int i = 0; i < 4; i++) { s0[i] = 0.f; s1[i] = 0.f; }
#pragma unroll 16
        for (int d = 0; d < HD; d++) {
            float b0 = Kt[d][tx * 2 + 0];
            float b1 = Kt[d][tx * 2 + 1];
#pragma unroll
            for (int i = 0; i < 4; i++) {
                float a = Qs[d][ty * 4 + i];
                s0[i] = fmaf(a, b0, s0[i]);
                s1[i] = fmaf(a, b1, s1[i]);
            }
        }

        // online softmax per row (reduce over 16 tx lanes)
#pragma unroll
        for (int i = 0; i < 4; i++) {
            float rm = fmaxf(s0[i], s1[i]);
#pragma unroll
            for (int off = 1; off < 16; off <<= 1)
                rm = fmaxf(rm, __shfl_xor_sync(0xffffffffu, rm, off));
            float mn   = fmaxf(mrow[i], rm);
            float corr = __expf(mrow[i] - mn);
            float p0   = __expf(s0[i] - mn);
            float p1   = __expf(s1[i] - mn);
            float rs   = p0 + p1;
#pragma unroll
            for (int off = 1; off < 16; off <<= 1)
                rs += __shfl_xor_sync(0xffffffffu, rs, off);
            lrow[i] = lrow[i] * corr + rs;
            mrow[i] = mn;
#pragma unroll
            for (int j = 0; j < 4; j++) o[i][j] *= corr;
            Ps[tx * 2 + 0][ty * 4 + i] = p0;
            Ps[tx * 2 + 1][ty * 4 + i] = p1;
        }
        __syncthreads();

        // O += P @ V  (rows ty*4.., d-cols tx*4..)
#pragma unroll 8
        for (int c = 0; c < FBK; c++) {
            float4 vv = *reinterpret_cast<const float4*>(&Vs[c][tx * 4]);
            float p0 = Ps[c][ty * 4 + 0];
            float p1 = Ps[c][ty * 4 + 1];
            float p2 = Ps[c][ty * 4 + 2];
            float p3 = Ps[c][ty * 4 + 3];
            o[0][0] = fmaf(p0, vv.x, o[0][0]); o[0][1] = fmaf(p0, vv.y, o[0][1]);
            o[0][2] = fmaf(p0, vv.z, o[0][2]); o[0][3] = fmaf(p0, vv.w, o[0][3]);
            o[1][0] = fmaf(p1, vv.x, o[1][0]); o[1][1] = fmaf(p1, vv.y, o[1][1]);
            o[1][2] = fmaf(p1, vv.z, o[1][2]); o[1][3] = fmaf(p1, vv.w, o[1][3]);
            o[2][0] = fmaf(p2, vv.x, o[2][0]); o[2][1] = fmaf(p2, vv.y, o[2][1]);
            o[2][2] = fmaf(p2, vv.z, o[2][2]); o[2][3] = fmaf(p2, vv.w, o[2][3]);
            o[3][0] = fmaf(p3, vv.x, o[3][0]); o[3][1] = fmaf(p3, vv.y, o[3][1]);
            o[3][2] = fmaf(p3, vv.z, o[3][2]); o[3][3] = fmaf(p3, vv.w, o[3][3]);
        }
    }

    // write back: [token][dim] layout, merging heads
    const int b_ = bh >> 4;
    const int h_ = bh & 15;
#pragma unroll
    for (int i = 0; i < 4; i++) {
        float inv = 1.f / lrow[i];
        int row = q0 + ty * 4 + i;
#pragma unroll
        for (int j = 0; j < 4; j++) {
            out[(size_t)(b_ * SEQ + row) * DIM + h_ * HD + tx * 4 + j] =
                o[i][j] * inv;
        }
    }
}

// ---------------- launcher ---------------------------------------------------
extern "C" void kernel_launch(void* const* d_in, const int* in_sizes, int n_in,
                              void* d_out, int out_size)
{
    const float* x  = (const float*)d_in[0];
    const float* wq = (const float*)d_in[1];
    const float* wk = (const float*)d_in[2];
    const float* wv = (const float*)d_in[3];
    const float* wo = (const float*)d_in[4];
    const float* w1 = (const float*)d_in[5];
    const float* w2 = (const float*)d_in[6];
    float* out = (float*)d_out;

    float *q, *k, *v, *attn, *x1, *hbuf;
    cudaGetSymbolAddress((void**)&q,    g_q);
    cudaGetSymbolAddress((void**)&k,    g_k);
    cudaGetSymbolAddress((void**)&v,    g_v);
    cudaGetSymbolAddress((void**)&attn, g_attn);
    cudaGetSymbolAddress((void**)&x1,   g_x1);
    cudaGetSymbolAddress((void**)&hbuf, g_hbuf);

    dim3 blk(256);

    // QKV projections with head-scatter epilogue
    gemm_k<<<dim3(DIM / TBN, NTOK / TBM), blk>>>(x, wq, nullptr, q,
                                                 NTOK, DIM, DIM, EPI_SCATTER);
    gemm_k<<<dim3(DIM / TBN, NTOK / TBM), blk>>>(x, wk, nullptr, k,
                                                 NTOK, DIM, DIM, EPI_SCATTER);
    gemm_k<<<dim3(DIM / TBN, NTOK / TBM), blk>>>(x, wv, nullptr, v,
                                                 NTOK, DIM, DIM, EPI_SCATTER);

    // fused attention
    flash_k<<<dim3(SEQ / FBQ, BATCH * NH), blk>>>(q, k, v, attn);

    // output projection + residual
    gemm_k<<<dim3(DIM / TBN, NTOK / TBM), blk>>>(attn, wo, x, x1,
                                                 NTOK, DIM, DIM, EPI_RES);
    // FFN up + relu
    gemm_k<<<dim3(FFN / TBN, NTOK / TBM), blk>>>(x1, w1, nullptr, hbuf,
                                                 NTOK, FFN, DIM, EPI_RELU);
    // FFN down + residual -> final output
    gemm_k<<<dim3(DIM / TBN, NTOK / TBM), blk>>>(hbuf, w2, x1, out,
                                                 NTOK, DIM, FFN, EPI_RES);
}

// round 3
// speedup vs baseline: 2.5039x; 2.5039x over previous
#include <cuda_runtime.h>
#include <cstdint>
#include <math.h>

// ---------------- problem sizes ----------------
#define DIM   1024
#define NH    16
#define HD    64
#define SEQ   2048
#define BATCH 2
#define NTOK  (BATCH*SEQ)   // 4096
#define FFN   (4*DIM)       // 4096

// ---------------- scratch (static device globals) ----------------
__device__ float g_q [(size_t)NTOK*DIM];           // [bh][s][64]
__device__ float g_k [(size_t)NTOK*DIM];           // [bh][s][64]
__device__ float g_vt[(size_t)NTOK*DIM];           // [bh][d][s]  (V transposed)
__device__ float g_attn[(size_t)NTOK*DIM];         // [token][dim]
__device__ float g_x1 [(size_t)NTOK*DIM];
__device__ float g_h  [(size_t)NTOK*FFN];
__device__ float g_S  [(size_t)BATCH*NH*SEQ*SEQ];  // exp(scores)
__device__ float g_lp [(size_t)BATCH*NH*SEQ*64];   // partial row sums (64 n-tiles)
__device__ float g_wqT[DIM*DIM], g_wkT[DIM*DIM], g_wvT[DIM*DIM], g_woT[DIM*DIM];
__device__ float g_w1T[(size_t)DIM*FFN];
__device__ float g_w2T[(size_t)DIM*FFN];

// ---------------- helpers ----------------
__device__ __forceinline__ uint32_t tf32c(float f) {
    uint32_t r;
    asm("cvt.rna.tf32.f32 %0, %1;" : "=r"(r) : "f"(f));
    return r;
}

__device__ __forceinline__ void mma8(float* c, const uint32_t* a,
                                     const uint32_t* b) {
    asm volatile(
        "mma.sync.aligned.m16n8k8.row.col.f32.tf32.tf32.f32 "
        "{%0,%1,%2,%3}, {%4,%5,%6,%7}, {%8,%9}, {%0,%1,%2,%3};"
        : "+f"(c[0]), "+f"(c[1]), "+f"(c[2]), "+f"(c[3])
        : "r"(a[0]), "r"(a[1]), "r"(a[2]), "r"(a[3]),
          "r"(b[0]), "r"(b[1]));
}

// ---------------- tf32 HMMA GEMM: C = epi(A[M,K] @ Bt[N,K]^T) ----------------
#define EPI_PLAIN 0
#define EPI_RES   1
#define EPI_RELU  2
#define EPI_QK    3   // scatter to [bh][s][64]
#define EPI_VT    4   // scatter to [bh][d][s]
#define EPI_EXPS  5   // store exp(v*scale), write partial row sums
#define EPI_ATTNO 6   // normalize by row sum, scatter to [token][dim]

// Block tile 128 x TN, K-chunk 16. 256 threads = 8 warps in 2x4 layout,
// warp tile 64 x (TN/4). m16n8k8 tf32 MMA.
template<int TN>
__global__ __launch_bounds__(256) void gemm_mma(
    const float* __restrict__ A, const float* __restrict__ B,
    const float* __restrict__ res, float* __restrict__ C,
    int K, int lda, int ldb, int ldc,
    size_t abatch, size_t bbatch, size_t cbatch, int epi)
{
    constexpr int WN = TN / 4;    // warp n-width (32 or 16)
    constexpr int NI = WN / 8;    // n8 tiles per warp (4 or 2)
    constexpr int NB = TN / 64;   // B float4 loads per thread (2 or 1)

    __shared__ uint32_t As[2][128][20];
    __shared__ uint32_t Bs[2][TN][20];
    __shared__ float linv[128];

    const int tid  = threadIdx.x;
    const int lane = tid & 31, wid = tid >> 5;
    const int wm   = wid >> 2,  wn  = wid & 3;
    const int grp  = lane >> 2, qid = lane & 3;
    const int bm   = blockIdx.y * 128, bn = blockIdx.x * TN;
    const int z    = blockIdx.z;

    const float* Ag = A + (size_t)z * abatch;
    const float* Bg = B + (size_t)z * bbatch;

    float acc[4][NI][4];
#pragma unroll
    for (int mi = 0; mi < 4; mi++)
#pragma unroll
        for (int ni = 0; ni < NI; ni++)
#pragma unroll
            for (int r = 0; r < 4; r++) acc[mi][ni][r] = 0.f;

    const int nk = K >> 4;
    uint4 ra[2], rb[NB];

    // ---- staged global->reg loads (tf32-converted) ----
#define LOAD_A(kt)                                                          \
    _Pragma("unroll")                                                       \
    for (int i = 0; i < 2; i++) {                                           \
        int f = tid + (i << 8), r_ = f >> 2, kq = (f & 3) << 2;             \
        float4 v = *reinterpret_cast<const float4*>(                        \
            Ag + (size_t)(bm + r_) * lda + ((kt) << 4) + kq);               \
        ra[i].x = tf32c(v.x); ra[i].y = tf32c(v.y);                         \
        ra[i].z = tf32c(v.z); ra[i].w = tf32c(v.w);                         \
    }
#define LOAD_B(kt)                                                          \
    _Pragma("unroll")                                                       \
    for (int i = 0; i < NB; i++) {                                          \
        int f = tid + (i << 8), r_ = f >> 2, kq = (f & 3) << 2;             \
        float4 v = *reinterpret_cast<const float4*>(                        \
            Bg + (size_t)(bn + r_) * ldb + ((kt) << 4) + kq);               \
        rb[i].x = tf32c(v.x); rb[i].y = tf32c(v.y);                         \
        rb[i].z = tf32c(v.z); rb[i].w = tf32c(v.w);                         \
    }
#define STORE_SM(buf)                                                       \
    _Pragma("unroll")                                                       \
    for (int i = 0; i < 2; i++) {                                           \
        int f = tid + (i << 8), r_ = f >> 2, kq = (f & 3) << 2;             \
        *reinterpret_cast<uint4*>(&As[buf][r_][kq]) = ra[i];                \
    }                                                                       \
    _Pragma("unroll")                                                       \
    for (int i = 0; i < NB; i++) {                                          \
        int f = tid + (i << 8), r_ = f >> 2, kq = (f & 3) << 2;             \
        *reinterpret_cast<uint4*>(&Bs[buf][r_][kq]) = rb[i];                \
    }

    LOAD_A(0); LOAD_B(0); STORE_SM(0);
    __syncthreads();

    for (int kt = 0; kt < nk; kt++) {
        const int cur = kt & 1;
        if (kt + 1 < nk) { LOAD_A(kt + 1); LOAD_B(kt + 1); }

#pragma unroll
        for (int ks = 0; ks < 16; ks += 8) {
            uint32_t af[4][4];
#pragma unroll
            for (int mi = 0; mi < 4; mi++) {
                int r0 = wm * 64 + mi * 16 + grp;
                af[mi][0] = As[cur][r0    ][ks + qid];
                af[mi][1] = As[cur][r0 + 8][ks + qid];
                af[mi][2] = As[cur][r0    ][ks + qid + 4];
                af[mi][3] = As[cur][r0 + 8][ks + qid + 4];
            }
            uint32_t bf[NI][2];
#pragma unroll
            for (int ni = 0; ni < NI; ni++) {
                int n0 = wn * WN + ni * 8 + grp;
                bf[ni][0] = Bs[cur][n0][ks + qid];
                bf[ni][1] = Bs[cur][n0][ks + qid + 4];
            }
#pragma unroll
            for (int mi = 0; mi < 4; mi++)
#pragma unroll
                for (int ni = 0; ni < NI; ni++)
                    mma8(acc[mi][ni], af[mi], bf[ni]);
        }

        if (kt + 1 < nk) {
            STORE_SM(cur ^ 1);
            __syncthreads();
        }
    }

    // ---------------- epilogue ----------------
    if (epi == EPI_ATTNO) {
        if (tid < 128) {
            const float* lp = g_lp + ((size_t)z * SEQ + bm + tid) * 64;
            float s = 0.f;
#pragma unroll
            for (int i = 0; i < 64; i++) s += lp[i];
            linv[tid] = 1.f / s;
        }
        __syncthreads();
    }

#pragma unroll
    for (int mi = 0; mi < 4; mi++) {
        const int r0g = bm + wm * 64 + mi * 16 + grp;
        const int r1g = r0g + 8;
        float rs0 = 0.f, rs1 = 0.f;

#pragma unroll
        for (int ni = 0; ni < NI; ni++) {
            const int cg = bn + wn * WN + ni * 8 + qid * 2;
            float v00 = acc[mi][ni][0], v01 = acc[mi][ni][1];
            float v10 = acc[mi][ni][2], v11 = acc[mi][ni][3];

            if (epi == EPI_EXPS) {
                float e00 = __expf(v00 * 0.125f), e01 = __expf(v01 * 0.125f);
                float e10 = __expf(v10 * 0.125f), e11 = __expf(v11 * 0.125f);
                rs0 += e00 + e01; rs1 += e10 + e11;
                float* d0 = C + (size_t)z * cbatch + (size_t)r0g * ldc + cg;
                float* d1 = C + (size_t)z * cbatch + (size_t)r1g * ldc + cg;
                *reinterpret_cast<float2*>(d0) = make_float2(e00, e01);
                *reinterpret_cast<float2*>(d1) = make_float2(e10, e11);
            } else if (epi == EPI_QK) {
                const int h_ = cg >> 6, d_ = cg & 63;
                {
                    int b_ = r0g >> 11, s_ = r0g & (SEQ - 1);
                    float* d0 = C + (((size_t)(b_ * NH + h_)) * SEQ + s_) * HD + d_;
                    *reinterpret_cast<float2*>(d0) = make_float2(v00, v01);
                }
                {
                    int b_ = r1g >> 11, s_ = r1g & (SEQ - 1);
                    float* d1 = C + (((size_t)(b_ * NH + h_)) * SEQ + s_) * HD + d_;
                    *reinterpret_cast<float2*>(d1) = make_float2(v10, v11);
                }
            } else if (epi == EPI_VT) {
                const int h_ = cg >> 6, d_ = cg & 63;
                {
                    int b_ = r0g >> 11, s_ = r0g & (SEQ - 1);
                    C[(((size_t)(b_ * NH + h_)) * HD + d_    ) * SEQ + s_] = v00;
                    C[(((size_t)(b_ * NH + h_)) * HD + d_ + 1) * SEQ + s_] = v01;
                }
                {
                    int b_ = r1g >> 11, s_ = r1g & (SEQ - 1);
                    C[(((size_t)(b_ * NH + h_)) * HD + d_    ) * SEQ + s_] = v10;
                    C[(((size_t)(b_ * NH + h_)) * HD + d_ + 1) * SEQ + s_] = v11;
                }
            } else if (epi == EPI_ATTNO) {
                const int b_ = z >> 4, h_ = z & 15;
                float i0 = linv[r0g - bm], i1 = linv[r1g - bm];
                float* d0 = C + ((size_t)b_ * SEQ + r0g) * DIM + h_ * HD + cg;
                float* d1 = C + ((size_t)b_ * SEQ + r1g) * DIM + h_ * HD + cg;
                *reinterpret_cast<float2*>(d0) = make_float2(v00 * i0, v01 * i0);
                *reinterpret_cast<float2*>(d1) = make_float2(v10 * i1, v11 * i1);
            } else {
                float* d0 = C + (size_t)z * cbatch + (size_t)r0g * ldc + cg;
                float* d1 = C + (size_t)z * cbatch + (size_t)r1g * ldc + cg;
                if (epi == EPI_RES) {
                    const float* q0 = res + (size_t)z * cbatch + (size_t)r0g * ldc + cg;
                    const float* q1 = res + (size_t)z * cbatch + (size_t)r1g * ldc + cg;
                    float2 a0 = *reinterpret_cast<const float2*>(q0);
                    float2 a1 = *reinterpret_cast<const float2*>(q1);
                    v00 += a0.x; v01 += a0.y; v10 += a1.x; v11 += a1.y;
                } else if (epi == EPI_RELU) {
                    v00 = fmaxf(v00, 0.f); v01 = fmaxf(v01, 0.f);
                    v10 = fmaxf(v10, 0.f); v11 = fmaxf(v11, 0.f);
                }
                *reinterpret_cast<float2*>(d0) = make_float2(v00, v01);
                *reinterpret_cast<float2*>(d1) = make_float2(v10, v11);
            }
        }

        if (epi == EPI_EXPS) {
            rs0 += __shfl_xor_sync(0xffffffffu, rs0, 1);
            rs0 += __shfl_xor_sync(0xffffffffu, rs0, 2);
            rs1 += __shfl_xor_sync(0xffffffffu, rs1, 1);
            rs1 += __shfl_xor_sync(0xffffffffu, rs1, 2);
            if (qid == 0) {
                int t = blockIdx.x * 4 + wn;
                g_lp[((size_t)z * SEQ + r0g) * 64 + t] = rs0;
                g_lp[((size_t)z * SEQ + r1g) * 64 + t] = rs1;
            }
        }
    }
}

// ---------------- transpose: dst[C][R] = src[R][C] ----------------
__global__ __launch_bounds__(256) void transpose_k(
    const float* __restrict__ S, float* __restrict__ D, int R, int Ccols)
{
    __shared__ float t[32][33];
    const int bx = blockIdx.x << 5, by = blockIdx.y << 5;
    const int tx = threadIdx.x;
#pragma unroll
    for (int i = threadIdx.y; i < 32; i += 8)
        t[i][tx] = S[(size_t)(by + i) * Ccols + bx + tx];
    __syncthreads();
#pragma unroll
    for (int i = threadIdx.y; i < 32; i += 8)
        D[(size_t)(bx + i) * R + by + tx] = t[tx][i];
}

// ---------------- launcher ----------------
extern "C" void kernel_launch(void* const* d_in, const int* in_sizes, int n_in,
                              void* d_out, int out_size)
{
    const float* x  = (const float*)d_in[0];
    const float* wq = (const float*)d_in[1];
    const float* wk = (const float*)d_in[2];
    const float* wv = (const float*)d_in[3];
    const float* wo = (const float*)d_in[4];
    const float* w1 = (const float*)d_in[5];
    const float* w2 = (const float*)d_in[6];
    float* out = (float*)d_out;

    float *q, *k, *vt, *attn, *x1, *h, *S;
    float *wqT, *wkT, *wvT, *woT, *w1T, *w2T;
    cudaGetSymbolAddress((void**)&q,    g_q);
    cudaGetSymbolAddress((void**)&k,    g_k);
    cudaGetSymbolAddress((void**)&vt,   g_vt);
    cudaGetSymbolAddress((void**)&attn, g_attn);
    cudaGetSymbolAddress((void**)&x1,   g_x1);
    cudaGetSymbolAddress((void**)&h,    g_h);
    cudaGetSymbolAddress((void**)&S,    g_S);
    cudaGetSymbolAddress((void**)&wqT,  g_wqT);
    cudaGetSymbolAddress((void**)&wkT,  g_wkT);
    cudaGetSymbolAddress((void**)&wvT,  g_wvT);
    cudaGetSymbolAddress((void**)&woT,  g_woT);
    cudaGetSymbolAddress((void**)&w1T,  g_w1T);
    cudaGetSymbolAddress((void**)&w2T,  g_w2T);

    dim3 tb(32, 8);
    transpose_k<<<dim3(32, 32),  tb>>>(wq, wqT, DIM, DIM);
    transpose_k<<<dim3(32, 32),  tb>>>(wk, wkT, DIM, DIM);
    transpose_k<<<dim3(32, 32),  tb>>>(wv, wvT, DIM, DIM);
    transpose_k<<<dim3(32, 32),  tb>>>(wo, woT, DIM, DIM);
    transpose_k<<<dim3(128, 32), tb>>>(w1, w1T, DIM, FFN);   // -> [4096][1024]
    transpose_k<<<dim3(32, 128), tb>>>(w2, w2T, FFN, DIM);   // -> [1024][4096]

    // QKV projections (M=4096, N=1024, K=1024)
    gemm_mma<128><<<dim3(8, 32, 1), 256>>>(
        x, wqT, nullptr, q, DIM, DIM, DIM, 0, 0, 0, 0, EPI_QK);
    gemm_mma<128><<<dim3(8, 32, 1), 256>>>(
        x, wkT, nullptr, k, DIM, DIM, DIM, 0, 0, 0, 0, EPI_QK);
    gemm_mma<128><<<dim3(8, 32, 1), 256>>>(
        x, wvT, nullptr, vt, DIM, DIM, DIM, 0, 0, 0, 0, EPI_VT);

    // scores: E = exp(Q K^T * scale), batched over 32 heads
    gemm_mma<128><<<dim3(16, 16, BATCH * NH), 256>>>(
        q, k, nullptr, S, HD, HD, HD, SEQ,
        (size_t)SEQ * HD, (size_t)SEQ * HD, (size_t)SEQ * SEQ, EPI_EXPS);

    // PV: O = (E / rowsum) V, batched (M=2048, N=64, K=2048)
    gemm_mma<64><<<dim3(1, 16, BATCH * NH), 256>>>(
        S, vt, nullptr, attn, SEQ, SEQ, SEQ, 0,
        (size_t)SEQ * SEQ, (size_t)HD * SEQ, 0, EPI_ATTNO);

    // WO + residual
    gemm_mma<128><<<dim3(8, 32, 1), 256>>>(
        attn, woT, x, x1, DIM, DIM, DIM, DIM, 0, 0, 0, EPI_RES);
    // FFN up + relu
    gemm_mma<128><<<dim3(32, 32, 1), 256>>>(
        x1, w1T, nullptr, h, DIM, DIM, DIM, FFN, 0, 0, 0, EPI_RELU);
    // FFN down + residual -> out
    gemm_mma<128><<<dim3(8, 32, 1), 256>>>(
        h, w2T, x1, out, FFN, FFN, FFN, DIM, 0, 0, 0, EPI_RES);
}

// round 4
// speedup vs baseline: 2.9226x; 1.1672x over previous
#include <cuda_runtime.h>
#include <cstdint>
#include <math.h>

// ---------------- problem sizes ----------------
#define DIM   1024
#define NH    16
#define HD    64
#define SEQ   2048
#define BATCH 2
#define NTOK  (BATCH*SEQ)   // 4096
#define FFN   (4*DIM)       // 4096

// ---------------- scratch (static device globals) ----------------
__device__ float g_q [(size_t)NTOK*DIM];           // [bh][s][64] tf32, prescaled
__device__ float g_k [(size_t)NTOK*DIM];           // [bh][s][64] tf32
__device__ float g_vt[(size_t)NTOK*DIM];           // [bh][d][s]  tf32 (V^T)
__device__ float g_attn[(size_t)NTOK*DIM];         // [token][dim]
__device__ float g_x1 [(size_t)NTOK*DIM];
__device__ float g_h  [(size_t)NTOK*FFN];
__device__ float g_wqT[DIM*DIM], g_wkT[DIM*DIM], g_wvT[DIM*DIM], g_woT[DIM*DIM];
__device__ float g_w1T[(size_t)DIM*FFN];
__device__ float g_w2T[(size_t)DIM*FFN];

// ---------------- helpers ----------------
__device__ __forceinline__ uint32_t tf32c(float f) {
    uint32_t r;
    asm("cvt.rna.tf32.f32 %0, %1;" : "=r"(r) : "f"(f));
    return r;
}

__device__ __forceinline__ void mma8(float* c, const uint32_t* a,
                                     const uint32_t* b) {
    asm volatile(
        "mma.sync.aligned.m16n8k8.row.col.f32.tf32.tf32.f32 "
        "{%0,%1,%2,%3}, {%4,%5,%6,%7}, {%8,%9}, {%0,%1,%2,%3};"
        : "+f"(c[0]), "+f"(c[1]), "+f"(c[2]), "+f"(c[3])
        : "r"(a[0]), "r"(a[1]), "r"(a[2]), "r"(a[3]),
          "r"(b[0]), "r"(b[1]));
}

__device__ __forceinline__ void cp16(float* dst, const float* src) {
    uint32_t d = (uint32_t)__cvta_generic_to_shared(dst);
    asm volatile("cp.async.ca.shared.global [%0], [%1], 16;"
                 :: "r"(d), "l"(src));
}
#define CP_COMMIT() asm volatile("cp.async.commit_group;" ::: "memory")
#define CP_WAIT1()  asm volatile("cp.async.wait_group 1;"  ::: "memory")
#define CP_WAIT0()  asm volatile("cp.async.wait_group 0;"  ::: "memory")

// ================= fused attention =================
// grid (SEQ/128, BATCH*NH), 128 threads (4 warps), warp tile 32 q-rows.
// Per k-tile (128 kv cols): S = Q K^T (tf32 mma), P = exp(S) in regs,
// O += P V via mma with P re-fragmented by warp shuffles. exp-sum in regs.
#define QS_STRIDE 68
#define VS_STRIDE 132
#define QS_FLOATS (128*QS_STRIDE)       // 8704
#define VS_FLOATS (64*VS_STRIDE)        // 8448
#define ATTN_SMEM ((QS_FLOATS + 2*QS_FLOATS + 2*VS_FLOATS)*4)  // 172032 B

__device__ __forceinline__ void pf_kv(float* Kd, float* Vd,
                                      const float* kb, const float* vb,
                                      int kk, int tid)
{
#pragma unroll
    for (int i = 0; i < 16; i++) {
        int f = (i << 7) + tid;
        int r = f >> 4, c4 = (f & 15) << 2;
        cp16(Kd + r * QS_STRIDE + c4, kb + (size_t)(kk + r) * HD + c4);
    }
#pragma unroll
    for (int i = 0; i < 16; i++) {
        int f = (i << 7) + tid;
        int r = f >> 5, c4 = (f & 31) << 2;
        cp16(Vd + r * VS_STRIDE + c4, vb + (size_t)r * SEQ + kk + c4);
    }
}

__global__ __launch_bounds__(128, 1) void attn_fused(
    const float* __restrict__ q, const float* __restrict__ k,
    const float* __restrict__ v, float* __restrict__ out)
{
    extern __shared__ float sm[];
    float* Qs = sm;
    float* Ks = sm + QS_FLOATS;
    float* Vs = sm + 3 * QS_FLOATS;

    const int tid  = threadIdx.x;
    const int lane = tid & 31, w = tid >> 5;
    const int grp  = lane >> 2, qid = lane & 3;
    const int bh   = blockIdx.y;
    const int q0   = blockIdx.x * 128;

    const float* qb = q + (size_t)bh * SEQ * HD;
    const float* kb = k + (size_t)bh * SEQ * HD;
    const float* vb = v + (size_t)bh * HD * SEQ;

    // group 0: Q tile + K0 + V0
#pragma unroll
    for (int i = 0; i < 16; i++) {
        int f = (i << 7) + tid;
        int r = f >> 4, c4 = (f & 15) << 2;
        cp16(Qs + r * QS_STRIDE + c4, qb + (size_t)(q0 + r) * HD + c4);
    }
    pf_kv(Ks, Vs, kb, vb, 0, tid);
    CP_COMMIT();

    float oacc[2][8][4];
    float rs[2][2] = {{0.f, 0.f}, {0.f, 0.f}};
#pragma unroll
    for (int mi = 0; mi < 2; mi++)
#pragma unroll
        for (int nd = 0; nd < 8; nd++)
#pragma unroll
            for (int r = 0; r < 4; r++) oacc[mi][nd][r] = 0.f;

    const int srcA = (grp << 2) | (qid >> 1);
    const int srcB = srcA | 2;
    const int sel  = qid & 1;

    for (int t = 0; t < 16; t++) {
        const int cur = t & 1;
        if (t + 1 < 16) {
            pf_kv(Ks + (cur ^ 1) * QS_FLOATS, Vs + (cur ^ 1) * VS_FLOATS,
                  kb, vb, (t + 1) << 7, tid);
            CP_COMMIT();
            CP_WAIT1();
        } else {
            CP_WAIT0();
        }
        __syncthreads();

        const float* Kc = Ks + cur * QS_FLOATS;
        const float* Vc = Vs + cur * VS_FLOATS;

#pragma unroll
        for (int h = 0; h < 2; h++) {
            // ---- S = Q K^T for 64 kv-cols of this half ----
            float p[2][8][4];
#pragma unroll
            for (int mi = 0; mi < 2; mi++)
#pragma unroll
                for (int ni = 0; ni < 8; ni++)
#pragma unroll
                    for (int r = 0; r < 4; r++) p[mi][ni][r] = 0.f;

#pragma unroll
            for (int ks = 0; ks < 8; ks++) {
                const int kbq = ks * 8;
                uint32_t af[2][4];
#pragma unroll
                for (int mi = 0; mi < 2; mi++) {
                    const int r0 = (w * 32 + mi * 16 + grp) * QS_STRIDE + kbq;
                    af[mi][0] = __float_as_uint(Qs[r0 + qid]);
                    af[mi][1] = __float_as_uint(Qs[r0 + 8 * QS_STRIDE + qid]);
                    af[mi][2] = __float_as_uint(Qs[r0 + qid + 4]);
                    af[mi][3] = __float_as_uint(Qs[r0 + 8 * QS_STRIDE + qid + 4]);
                }
#pragma unroll
                for (int ni = 0; ni < 8; ni++) {
                    const int n0 = (h * 64 + ni * 8 + grp) * QS_STRIDE + kbq;
                    uint32_t bf[2] = { __float_as_uint(Kc[n0 + qid]),
                                       __float_as_uint(Kc[n0 + qid + 4]) };
                    mma8(p[0][ni], af[0], bf);
                    mma8(p[1][ni], af[1], bf);
                }
            }

            // ---- P = exp(S), accumulate row sums ----
#pragma unroll
            for (int mi = 0; mi < 2; mi++)
#pragma unroll
                for (int ni = 0; ni < 8; ni++) {
                    float e0 = __expf(p[mi][ni][0]);
                    float e1 = __expf(p[mi][ni][1]);
                    float e2 = __expf(p[mi][ni][2]);
                    float e3 = __expf(p[mi][ni][3]);
                    p[mi][ni][0] = e0; p[mi][ni][1] = e1;
                    p[mi][ni][2] = e2; p[mi][ni][3] = e3;
                    rs[mi][0] += e0 + e1;
                    rs[mi][1] += e2 + e3;
                }

            // ---- O += P V : A-fragments of P via warp shuffles ----
#pragma unroll
            for (int j = 0; j < 8; j++) {
                uint32_t af2[2][4];
#pragma unroll
                for (int mi = 0; mi < 2; mi++) {
                    float t0 = __shfl_sync(0xffffffffu, p[mi][j][0], srcA);
                    float t1 = __shfl_sync(0xffffffffu, p[mi][j][1], srcA);
                    float t2 = __shfl_sync(0xffffffffu, p[mi][j][2], srcA);
                    float t3 = __shfl_sync(0xffffffffu, p[mi][j][3], srcA);
                    float u0 = __shfl_sync(0xffffffffu, p[mi][j][0], srcB);
                    float u1 = __shfl_sync(0xffffffffu, p[mi][j][1], srcB);
                    float u2 = __shfl_sync(0xffffffffu, p[mi][j][2], srcB);
                    float u3 = __shfl_sync(0xffffffffu, p[mi][j][3], srcB);
                    af2[mi][0] = tf32c(sel ? t1 : t0);
                    af2[mi][1] = tf32c(sel ? t3 : t2);
                    af2[mi][2] = tf32c(sel ? u1 : u0);
                    af2[mi][3] = tf32c(sel ? u3 : u2);
                }
                const int cb = h * 64 + j * 8;
#pragma unroll
                for (int nd = 0; nd < 8; nd++) {
                    const int n0 = (nd * 8 + grp) * VS_STRIDE + cb;
                    uint32_t bf[2] = { __float_as_uint(Vc[n0 + qid]),
                                       __float_as_uint(Vc[n0 + qid + 4]) };
                    mma8(oacc[0][nd], af2[0], bf);
                    mma8(oacc[1][nd], af2[1], bf);
                }
            }
        }
        __syncthreads();
    }

    // ---- normalize + write [token][dim] ----
    float inv[2][2];
#pragma unroll
    for (int mi = 0; mi < 2; mi++)
#pragma unroll
        for (int r = 0; r < 2; r++) {
            float s = rs[mi][r];
            s += __shfl_xor_sync(0xffffffffu, s, 1);
            s += __shfl_xor_sync(0xffffffffu, s, 2);
            inv[mi][r] = 1.f / s;
        }

    const int b_ = bh >> 4, h_ = bh & 15;
#pragma unroll
    for (int mi = 0; mi < 2; mi++) {
        const int r0 = q0 + w * 32 + mi * 16 + grp;
#pragma unroll
        for (int nd = 0; nd < 8; nd++) {
            const int c = nd * 8 + qid * 2;
            float* d0 = out + ((size_t)b_ * SEQ + r0) * DIM + h_ * HD + c;
            float* d1 = d0 + (size_t)8 * DIM;
            *reinterpret_cast<float2*>(d0) =
                make_float2(oacc[mi][nd][0] * inv[mi][0],
                            oacc[mi][nd][1] * inv[mi][0]);
            *reinterpret_cast<float2*>(d1) =
                make_float2(oacc[mi][nd][2] * inv[mi][1],
                            oacc[mi][nd][3] * inv[mi][1]);
        }
    }
}

// ---------------- tf32 HMMA GEMM: C = epi(A[M,K] @ Bt[N,K]^T) ----------------
#define EPI_PLAIN 0
#define EPI_RES   1
#define EPI_RELU  2
#define EPI_QK    3   // scatter to [bh][s][64], tf32-rounded, *escale
#define EPI_VT    4   // scatter to [bh][d][s], tf32-rounded

template<int TN>
__global__ __launch_bounds__(256) void gemm_mma(
    const float* __restrict__ A, const float* __restrict__ B,
    const float* __restrict__ res, float* __restrict__ C,
    int K, int lda, int ldb, int ldc, int epi, float escale)
{
    constexpr int WN = TN / 4;
    constexpr int NI = WN / 8;
    constexpr int NB = TN / 64;

    __shared__ uint32_t As[2][128][20];
    __shared__ uint32_t Bs[2][TN][20];

    const int tid  = threadIdx.x;
    const int lane = tid & 31, wid = tid >> 5;
    const int wm   = wid >> 2,  wn  = wid & 3;
    const int grp  = lane >> 2, qid = lane & 3;
    const int bm   = blockIdx.y * 128, bn = blockIdx.x * TN;

    float acc[4][NI][4];
#pragma unroll
    for (int mi = 0; mi < 4; mi++)
#pragma unroll
        for (int ni = 0; ni < NI; ni++)
#pragma unroll
            for (int r = 0; r < 4; r++) acc[mi][ni][r] = 0.f;

    const int nk = K >> 4;
    uint4 ra[2], rb[NB];

#define LOAD_A(kt)                                                          \
    _Pragma("unroll")                                                       \
    for (int i = 0; i < 2; i++) {                                           \
        int f = tid + (i << 8), r_ = f >> 2, kq = (f & 3) << 2;             \
        float4 v = *reinterpret_cast<const float4*>(                        \
            A + (size_t)(bm + r_) * lda + ((kt) << 4) + kq);                \
        ra[i].x = tf32c(v.x); ra[i].y = tf32c(v.y);                         \
        ra[i].z = tf32c(v.z); ra[i].w = tf32c(v.w);                         \
    }
#define LOAD_B(kt)                                                          \
    _Pragma("unroll")                                                       \
    for (int i = 0; i < NB; i++) {                                          \
        int f = tid + (i << 8), r_ = f >> 2, kq = (f & 3) << 2;             \
        float4 v = *reinterpret_cast<const float4*>(                        \
            B + (size_t)(bn + r_) * ldb + ((kt) << 4) + kq);                \
        rb[i].x = tf32c(v.x); rb[i].y = tf32c(v.y);                         \
        rb[i].z = tf32c(v.z); rb[i].w = tf32c(v.w);                         \
    }
#define STORE_SM(buf)                                                       \
    _Pragma("unroll")                                                       \
    for (int i = 0; i < 2; i++) {                                           \
        int f = tid + (i << 8), r_ = f >> 2, kq = (f & 3) << 2;             \
        *reinterpret_cast<uint4*>(&As[buf][r_][kq]) = ra[i];                \
    }                                                                       \
    _Pragma("unroll")                                                       \
    for (int i = 0; i < NB; i++) {                                          \
        int f = tid + (i << 8), r_ = f >> 2, kq = (f & 3) << 2;             \
        *reinterpret_cast<uint4*>(&Bs[buf][r_][kq]) = rb[i];                \
    }

    LOAD_A(0); LOAD_B(0); STORE_SM(0);
    __syncthreads();

    for (int kt = 0; kt < nk; kt++) {
        const int cur = kt & 1;
        if (kt + 1 < nk) { LOAD_A(kt + 1); LOAD_B(kt + 1); }

#pragma unroll
        for (int ks = 0; ks < 16; ks += 8) {
            uint32_t af[4][4];
#pragma unroll
            for (int mi = 0; mi < 4; mi++) {
                int r0 = wm * 64 + mi * 16 + grp;
                af[mi][0] = As[cur][r0    ][ks + qid];
                af[mi][1] = As[cur][r0 + 8][ks + qid];
                af[mi][2] = As[cur][r0    ][ks + qid + 4];
                af[mi][3] = As[cur][r0 + 8][ks + qid + 4];
            }
            uint32_t bf[NI][2];
#pragma unroll
            for (int ni = 0; ni < NI; ni++) {
                int n0 = wn * WN + ni * 8 + grp;
                bf[ni][0] = Bs[cur][n0][ks + qid];
                bf[ni][1] = Bs[cur][n0][ks + qid + 4];
            }
#pragma unroll
            for (int mi = 0; mi < 4; mi++)
#pragma unroll
                for (int ni = 0; ni < NI; ni++)
                    mma8(acc[mi][ni], af[mi], bf[ni]);
        }

        if (kt + 1 < nk) {
            STORE_SM(cur ^ 1);
            __syncthreads();
        }
    }

    // ---------------- epilogue ----------------
#pragma unroll
    for (int mi = 0; mi < 4; mi++) {
        const int r0g = bm + wm * 64 + mi * 16 + grp;
        const int r1g = r0g + 8;

#pragma unroll
        for (int ni = 0; ni < NI; ni++) {
            const int cg = bn + wn * WN + ni * 8 + qid * 2;
            float v00 = acc[mi][ni][0], v01 = acc[mi][ni][1];
            float v10 = acc[mi][ni][2], v11 = acc[mi][ni][3];

            if (epi == EPI_QK) {
                const int h_ = cg >> 6, d_ = cg & 63;
                float2 o0 = make_float2(
                    __uint_as_float(tf32c(v00 * escale)),
                    __uint_as_float(tf32c(v01 * escale)));
                float2 o1 = make_float2(
                    __uint_as_float(tf32c(v10 * escale)),
                    __uint_as_float(tf32c(v11 * escale)));
                {
                    int b_ = r0g >> 11, s_ = r0g & (SEQ - 1);
                    *reinterpret_cast<float2*>(
                        C + (((size_t)(b_ * NH + h_)) * SEQ + s_) * HD + d_) = o0;
                }
                {
                    int b_ = r1g >> 11, s_ = r1g & (SEQ - 1);
                    *reinterpret_cast<float2*>(
                        C + (((size_t)(b_ * NH + h_)) * SEQ + s_) * HD + d_) = o1;
                }
            } else if (epi == EPI_VT) {
                const int h_ = cg >> 6, d_ = cg & 63;
                {
                    int b_ = r0g >> 11, s_ = r0g & (SEQ - 1);
                    C[(((size_t)(b_ * NH + h_)) * HD + d_    ) * SEQ + s_] =
                        __uint_as_float(tf32c(v00));
                    C[(((size_t)(b_ * NH + h_)) * HD + d_ + 1) * SEQ + s_] =
                        __uint_as_float(tf32c(v01));
                }
                {
                    int b_ = r1g >> 11, s_ = r1g & (SEQ - 1);
                    C[(((size_t)(b_ * NH + h_)) * HD + d_    ) * SEQ + s_] =
                        __uint_as_float(tf32c(v10));
                    C[(((size_t)(b_ * NH + h_)) * HD + d_ + 1) * SEQ + s_] =
                        __uint_as_float(tf32c(v11));
                }
            } else {
                float* d0 = C + (size_t)r0g * ldc + cg;
                float* d1 = C + (size_t)r1g * ldc + cg;
                if (epi == EPI_RES) {
                    float2 a0 = *reinterpret_cast<const float2*>(
                        res + (size_t)r0g * ldc + cg);
                    float2 a1 = *reinterpret_cast<const float2*>(
                        res + (size_t)r1g * ldc + cg);
                    v00 += a0.x; v01 += a0.y; v10 += a1.x; v11 += a1.y;
                } else if (epi == EPI_RELU) {
                    v00 = fmaxf(v00, 0.f); v01 = fmaxf(v01, 0.f);
                    v10 = fmaxf(v10, 0.f); v11 = fmaxf(v11, 0.f);
                }
                *reinterpret_cast<float2*>(d0) = make_float2(v00, v01);
                *reinterpret_cast<float2*>(d1) = make_float2(v10, v11);
            }
        }
    }
}

// ---------------- transpose: dst[C][R] = src[R][C] ----------------
__global__ __launch_bounds__(256) void transpose_k(
    const float* __restrict__ S, float* __restrict__ D, int R, int Ccols)
{
    __shared__ float t[32][33];
    const int bx = blockIdx.x << 5, by = blockIdx.y << 5;
    const int tx = threadIdx.x;
#pragma unroll
    for (int i = threadIdx.y; i < 32; i += 8)
        t[i][tx] = S[(size_t)(by + i) * Ccols + bx + tx];
    __syncthreads();
#pragma unroll
    for (int i = threadIdx.y; i < 32; i += 8)
        D[(size_t)(bx + i) * R + by + tx] = t[tx][i];
}

// ---------------- launcher ----------------
extern "C" void kernel_launch(void* const* d_in, const int* in_sizes, int n_in,
                              void* d_out, int out_size)
{
    const float* x  = (const float*)d_in[0];
    const float* wq = (const float*)d_in[1];
    const float* wk = (const float*)d_in[2];
    const float* wv = (const float*)d_in[3];
    const float* wo = (const float*)d_in[4];
    const float* w1 = (const float*)d_in[5];
    const float* w2 = (const float*)d_in[6];
    float* out = (float*)d_out;

    float *q, *k, *vt, *attn, *x1, *h;
    float *wqT, *wkT, *wvT, *woT, *w1T, *w2T;
    cudaGetSymbolAddress((void**)&q,    g_q);
    cudaGetSymbolAddress((void**)&k,    g_k);
    cudaGetSymbolAddress((void**)&vt,   g_vt);
    cudaGetSymbolAddress((void**)&attn, g_attn);
    cudaGetSymbolAddress((void**)&x1,   g_x1);
    cudaGetSymbolAddress((void**)&h,    g_h);
    cudaGetSymbolAddress((void**)&wqT,  g_wqT);
    cudaGetSymbolAddress((void**)&wkT,  g_wkT);
    cudaGetSymbolAddress((void**)&wvT,  g_wvT);
    cudaGetSymbolAddress((void**)&woT,  g_woT);
    cudaGetSymbolAddress((void**)&w1T,  g_w1T);
    cudaGetSymbolAddress((void**)&w2T,  g_w2T);

    cudaFuncSetAttribute(attn_fused,
        cudaFuncAttributeMaxDynamicSharedMemorySize, ATTN_SMEM);

    dim3 tb(32, 8);
    transpose_k<<<dim3(32, 32),  tb>>>(wq, wqT, DIM, DIM);
    transpose_k<<<dim3(32, 32),  tb>>>(wk, wkT, DIM, DIM);
    transpose_k<<<dim3(32, 32),  tb>>>(wv, wvT, DIM, DIM);
    transpose_k<<<dim3(32, 32),  tb>>>(wo, woT, DIM, DIM);
    transpose_k<<<dim3(128, 32), tb>>>(w1, w1T, DIM, FFN);
    transpose_k<<<dim3(32, 128), tb>>>(w2, w2T, FFN, DIM);

    // QKV projections (M=4096, N=1024, K=1024); Q pre-scaled by 1/8
    gemm_mma<128><<<dim3(8, 32), 256>>>(
        x, wqT, nullptr, q, DIM, DIM, DIM, 0, EPI_QK, 0.125f);
    gemm_mma<128><<<dim3(8, 32), 256>>>(
        x, wkT, nullptr, k, DIM, DIM, DIM, 0, EPI_QK, 1.0f);
    gemm_mma<128><<<dim3(8, 32), 256>>>(
        x, wvT, nullptr, vt, DIM, DIM, DIM, 0, EPI_VT, 1.0f);

    // fused attention -> g_attn [token][dim]
    attn_fused<<<dim3(SEQ / 128, BATCH * NH), 128, ATTN_SMEM>>>(
        q, k, vt, attn);

    // WO + residual
    gemm_mma<128><<<dim3(8, 32), 256>>>(
        attn, woT, x, x1, DIM, DIM, DIM, DIM, EPI_RES, 1.0f);
    // FFN up + relu
    gemm_mma<128><<<dim3(32, 32), 256>>>(
        x1, w1T, nullptr, h, DIM, DIM, DIM, FFN, EPI_RELU, 1.0f);
    // FFN down + residual -> out
    gemm_mma<128><<<dim3(8, 32), 256>>>(
        h, w2T, x1, out, FFN, FFN, FFN, DIM, EPI_RES, 1.0f);
}

// round 5
// speedup vs baseline: 3.0894x; 1.0571x over previous
#include <cuda_runtime.h>
#include <cstdint>
#include <math.h>

// ---------------- problem sizes ----------------
#define DIM   1024
#define NH    16
#define HD    64
#define SEQ   2048
#define BATCH 2
#define NTOK  (BATCH*SEQ)   // 4096
#define FFN   (4*DIM)       // 4096

// ---------------- scratch (static device globals) ----------------
__device__ float g_q [(size_t)NTOK*DIM];           // [bh][s][64] tf32, prescaled
__device__ float g_k [(size_t)NTOK*DIM];           // [bh][s][64] tf32
__device__ float g_vt[(size_t)NTOK*DIM];           // [bh][d][s]  tf32 (V^T)
__device__ float g_attn[(size_t)NTOK*DIM];         // [token][dim] tf32-rounded
__device__ float g_x1 [(size_t)NTOK*DIM];
__device__ float g_h  [(size_t)NTOK*FFN];
__device__ float g_wqkvT[(size_t)3*DIM*DIM];       // [3][n][k] tf32
__device__ float g_woT[DIM*DIM];
__device__ float g_w1T[(size_t)DIM*FFN];
__device__ float g_w2T[(size_t)DIM*FFN];

// ---------------- helpers ----------------
__device__ __forceinline__ uint32_t tf32c(float f) {
    uint32_t r;
    asm("cvt.rna.tf32.f32 %0, %1;" : "=r"(r) : "f"(f));
    return r;
}
__device__ __forceinline__ float tf32f(float f) {
    return __uint_as_float(tf32c(f));
}

__device__ __forceinline__ void mma8(float* c, const uint32_t* a,
                                     const uint32_t* b) {
    asm volatile(
        "mma.sync.aligned.m16n8k8.row.col.f32.tf32.tf32.f32 "
        "{%0,%1,%2,%3}, {%4,%5,%6,%7}, {%8,%9}, {%0,%1,%2,%3};"
        : "+f"(c[0]), "+f"(c[1]), "+f"(c[2]), "+f"(c[3])
        : "r"(a[0]), "r"(a[1]), "r"(a[2]), "r"(a[3]),
          "r"(b[0]), "r"(b[1]));
}

__device__ __forceinline__ void cp16(float* dst, const float* src) {
    uint32_t d = (uint32_t)__cvta_generic_to_shared(dst);
    asm volatile("cp.async.ca.shared.global [%0], [%1], 16;"
                 :: "r"(d), "l"(src));
}
#define CP_COMMIT() asm volatile("cp.async.commit_group;" ::: "memory")
#define CP_WAIT2()  asm volatile("cp.async.wait_group 2;"  ::: "memory")
#define CP_WAIT1()  asm volatile("cp.async.wait_group 1;"  ::: "memory")
#define CP_WAIT0()  asm volatile("cp.async.wait_group 0;"  ::: "memory")

// ================= big-tile tf32 GEMM =================
// C[M,N] = epi(A[M,K] @ Bt[N,K]^T).  CTA tile 128x256, 256 thr = 8 warps
// (2 row-groups x 4 col-groups), warp tile 64x64. cp.async 3-stage, kc=16.
#define EPI_RES   1
#define EPI_RELU  2
#define EPI_QKV   3

#define AST 2560                 // floats per A stage: 128*20
#define BST 5120                 // floats per B stage: 256*20
#define GEMM_SMEM ((3*AST + 3*BST)*4)   // 92160 B

__device__ __forceinline__ void g2s(float* As, float* Bs,
                                    const float* A, const float* B,
                                    int bm, int bn, int lda, int ldb,
                                    int kk, int tid)
{
#pragma unroll
    for (int i = 0; i < 2; i++) {
        int c = tid + (i << 8);
        int r = c >> 2, kq = (c & 3) << 2;
        cp16(As + r * 20 + kq, A + (size_t)(bm + r) * lda + kk + kq);
    }
#pragma unroll
    for (int i = 0; i < 4; i++) {
        int c = tid + (i << 8);
        int r = c >> 2, kq = (c & 3) << 2;
        cp16(Bs + r * 20 + kq, B + (size_t)(bn + r) * ldb + kk + kq);
    }
}

__global__ __launch_bounds__(256, 1) void gemm256(
    const float* __restrict__ A, const float* __restrict__ B,
    const float* __restrict__ res, float* __restrict__ C,
    int K, int lda, int ldb, int ldc, int epi)
{
    extern __shared__ float sm[];
    float* Asm = sm;
    float* Bsm = sm + 3 * AST;

    const int tid  = threadIdx.x;
    const int lane = tid & 31, wid = tid >> 5;
    const int wm   = wid >> 2, wn = wid & 3;
    const int grp  = lane >> 2, qid = lane & 3;
    const int bm   = blockIdx.y * 128, bn = blockIdx.x * 256;

    float acc[4][8][4];
#pragma unroll
    for (int mi = 0; mi < 4; mi++)
#pragma unroll
        for (int ni = 0; ni < 8; ni++)
#pragma unroll
            for (int r = 0; r < 4; r++) acc[mi][ni][r] = 0.f;

    const int nk = K >> 4;

    g2s(Asm, Bsm, A, B, bm, bn, lda, ldb, 0, tid);
    CP_COMMIT();
    g2s(Asm + AST, Bsm + BST, A, B, bm, bn, lda, ldb, 16, tid);
    CP_COMMIT();

    int st2 = 2;   // stage index to fill next
    for (int kt = 0; kt < nk; kt++) {
        const int cur = kt - (kt / 3) * 3;           // kt % 3
        if (kt + 2 < nk)
            g2s(Asm + st2 * AST, Bsm + st2 * BST, A, B, bm, bn,
                lda, ldb, (kt + 2) << 4, tid);
        CP_COMMIT();
        if (++st2 == 3) st2 = 0;

        CP_WAIT2();
        __syncthreads();

        const float* Aw = Asm + cur * AST + (wm * 64) * 20;
        const float* Bw = Bsm + cur * BST + (wn * 64) * 20;

#pragma unroll
        for (int ks = 0; ks < 16; ks += 8) {
            uint32_t af[4][4];
#pragma unroll
            for (int mi = 0; mi < 4; mi++) {
                const int b0 = (mi * 16 + grp) * 20 + ks + qid;
                af[mi][0] = __float_as_uint(Aw[b0]);
                af[mi][1] = __float_as_uint(Aw[b0 + 160]);
                af[mi][2] = __float_as_uint(Aw[b0 + 4]);
                af[mi][3] = __float_as_uint(Aw[b0 + 164]);
            }
            uint32_t bf[8][2];
#pragma unroll
            for (int ni = 0; ni < 8; ni++) {
                const int n0 = (ni * 8 + grp) * 20 + ks + qid;
                bf[ni][0] = __float_as_uint(Bw[n0]);
                bf[ni][1] = __float_as_uint(Bw[n0 + 4]);
            }
#pragma unroll
            for (int mi = 0; mi < 4; mi++)
#pragma unroll
                for (int ni = 0; ni < 8; ni++)
                    mma8(acc[mi][ni], af[mi], bf[ni]);
        }
        __syncthreads();
    }

    // ---------------- epilogue ----------------
#pragma unroll
    for (int mi = 0; mi < 4; mi++) {
        const int r0g = bm + wm * 64 + mi * 16 + grp;
        const int r1g = r0g + 8;

#pragma unroll
        for (int ni = 0; ni < 8; ni++) {
            const int cg = bn + wn * 64 + ni * 8 + qid * 2;
            float v00 = acc[mi][ni][0], v01 = acc[mi][ni][1];
            float v10 = acc[mi][ni][2], v11 = acc[mi][ni][3];

            if (epi == EPI_QKV) {
                const int seg = cg >> 10;        // 0=Q 1=K 2=VT
                const int n_  = cg & 1023;
                const int h_  = n_ >> 6, d_ = n_ & 63;
                const int b0_ = r0g >> 11, s0_ = r0g & (SEQ - 1);
                const int b1_ = r1g >> 11, s1_ = r1g & (SEQ - 1);
                if (seg == 0) {
                    float* d0 = g_q + (((size_t)(b0_*NH + h_))*SEQ + s0_)*HD + d_;
                    float* d1 = g_q + (((size_t)(b1_*NH + h_))*SEQ + s1_)*HD + d_;
                    *reinterpret_cast<float2*>(d0) =
                        make_float2(tf32f(v00 * 0.125f), tf32f(v01 * 0.125f));
                    *reinterpret_cast<float2*>(d1) =
                        make_float2(tf32f(v10 * 0.125f), tf32f(v11 * 0.125f));
                } else if (seg == 1) {
                    float* d0 = g_k + (((size_t)(b0_*NH + h_))*SEQ + s0_)*HD + d_;
                    float* d1 = g_k + (((size_t)(b1_*NH + h_))*SEQ + s1_)*HD + d_;
                    *reinterpret_cast<float2*>(d0) =
                        make_float2(tf32f(v00), tf32f(v01));
                    *reinterpret_cast<float2*>(d1) =
                        make_float2(tf32f(v10), tf32f(v11));
                } else {
                    g_vt[(((size_t)(b0_*NH + h_))*HD + d_    )*SEQ + s0_] = tf32f(v00);
                    g_vt[(((size_t)(b0_*NH + h_))*HD + d_ + 1)*SEQ + s0_] = tf32f(v01);
                    g_vt[(((size_t)(b1_*NH + h_))*HD + d_    )*SEQ + s1_] = tf32f(v10);
                    g_vt[(((size_t)(b1_*NH + h_))*HD + d_ + 1)*SEQ + s1_] = tf32f(v11);
                }
            } else {
                float* d0 = C + (size_t)r0g * ldc + cg;
                float* d1 = C + (size_t)r1g * ldc + cg;
                if (epi == EPI_RES) {
                    float2 a0 = *reinterpret_cast<const float2*>(
                        res + (size_t)r0g * ldc + cg);
                    float2 a1 = *reinterpret_cast<const float2*>(
                        res + (size_t)r1g * ldc + cg);
                    v00 += a0.x; v01 += a0.y; v10 += a1.x; v11 += a1.y;
                } else {  // EPI_RELU, rounded for FFN2 consumption
                    v00 = tf32f(fmaxf(v00, 0.f)); v01 = tf32f(fmaxf(v01, 0.f));
                    v10 = tf32f(fmaxf(v10, 0.f)); v11 = tf32f(fmaxf(v11, 0.f));
                }
                *reinterpret_cast<float2*>(d0) = make_float2(v00, v01);
                *reinterpret_cast<float2*>(d1) = make_float2(v10, v11);
            }
        }
    }
}

// ================= fused attention (round-4, + tf32-rounded output) ========
#define QS_STRIDE 68
#define VS_STRIDE 132
#define QS_FLOATS (128*QS_STRIDE)
#define VS_FLOATS (64*VS_STRIDE)
#define ATTN_SMEM ((QS_FLOATS + 2*QS_FLOATS + 2*VS_FLOATS)*4)

__device__ __forceinline__ void pf_kv(float* Kd, float* Vd,
                                      const float* kb, const float* vb,
                                      int kk, int tid)
{
#pragma unroll
    for (int i = 0; i < 16; i++) {
        int f = (i << 7) + tid;
        int r = f >> 4, c4 = (f & 15) << 2;
        cp16(Kd + r * QS_STRIDE + c4, kb + (size_t)(kk + r) * HD + c4);
    }
#pragma unroll
    for (int i = 0; i < 16; i++) {
        int f = (i << 7) + tid;
        int r = f >> 5, c4 = (f & 31) << 2;
        cp16(Vd + r * VS_STRIDE + c4, vb + (size_t)r * SEQ + kk + c4);
    }
}

__global__ __launch_bounds__(128, 1) void attn_fused(
    const float* __restrict__ q, const float* __restrict__ k,
    const float* __restrict__ v, float* __restrict__ out)
{
    extern __shared__ float sm[];
    float* Qs = sm;
    float* Ks = sm + QS_FLOATS;
    float* Vs = sm + 3 * QS_FLOATS;

    const int tid  = threadIdx.x;
    const int lane = tid & 31, w = tid >> 5;
    const int grp  = lane >> 2, qid = lane & 3;
    const int bh   = blockIdx.y;
    const int q0   = blockIdx.x * 128;

    const float* qb = q + (size_t)bh * SEQ * HD;
    const float* kb = k + (size_t)bh * SEQ * HD;
    const float* vb = v + (size_t)bh * HD * SEQ;

#pragma unroll
    for (int i = 0; i < 16; i++) {
        int f = (i << 7) + tid;
        int r = f >> 4, c4 = (f & 15) << 2;
        cp16(Qs + r * QS_STRIDE + c4, qb + (size_t)(q0 + r) * HD + c4);
    }
    pf_kv(Ks, Vs, kb, vb, 0, tid);
    CP_COMMIT();

    float oacc[2][8][4];
    float rs[2][2] = {{0.f, 0.f}, {0.f, 0.f}};
#pragma unroll
    for (int mi = 0; mi < 2; mi++)
#pragma unroll
        for (int nd = 0; nd < 8; nd++)
#pragma unroll
            for (int r = 0; r < 4; r++) oacc[mi][nd][r] = 0.f;

    const int srcA = (grp << 2) | (qid >> 1);
    const int srcB = srcA | 2;
    const int sel  = qid & 1;

    for (int t = 0; t < 16; t++) {
        const int cur = t & 1;
        if (t + 1 < 16) {
            pf_kv(Ks + (cur ^ 1) * QS_FLOATS, Vs + (cur ^ 1) * VS_FLOATS,
                  kb, vb, (t + 1) << 7, tid);
            CP_COMMIT();
            CP_WAIT1();
        } else {
            CP_WAIT0();
        }
        __syncthreads();

        const float* Kc = Ks + cur * QS_FLOATS;
        const float* Vc = Vs + cur * VS_FLOATS;

#pragma unroll
        for (int h = 0; h < 2; h++) {
            float p[2][8][4];
#pragma unroll
            for (int mi = 0; mi < 2; mi++)
#pragma unroll
                for (int ni = 0; ni < 8; ni++)
#pragma unroll
                    for (int r = 0; r < 4; r++) p[mi][ni][r] = 0.f;

#pragma unroll
            for (int ks = 0; ks < 8; ks++) {
                const int kbq = ks * 8;
                uint32_t af[2][4];
#pragma unroll
                for (int mi = 0; mi < 2; mi++) {
                    const int r0 = (w * 32 + mi * 16 + grp) * QS_STRIDE + kbq;
                    af[mi][0] = __float_as_uint(Qs[r0 + qid]);
                    af[mi][1] = __float_as_uint(Qs[r0 + 8 * QS_STRIDE + qid]);
                    af[mi][2] = __float_as_uint(Qs[r0 + qid + 4]);
                    af[mi][3] = __float_as_uint(Qs[r0 + 8 * QS_STRIDE + qid + 4]);
                }
#pragma unroll
                for (int ni = 0; ni < 8; ni++) {
                    const int n0 = (h * 64 + ni * 8 + grp) * QS_STRIDE + kbq;
                    uint32_t bf[2] = { __float_as_uint(Kc[n0 + qid]),
                                       __float_as_uint(Kc[n0 + qid + 4]) };
                    mma8(p[0][ni], af[0], bf);
                    mma8(p[1][ni], af[1], bf);
                }
            }

#pragma unroll
            for (int mi = 0; mi < 2; mi++)
#pragma unroll
                for (int ni = 0; ni < 8; ni++) {
                    float e0 = __expf(p[mi][ni][0]);
                    float e1 = __expf(p[mi][ni][1]);
                    float e2 = __expf(p[mi][ni][2]);
                    float e3 = __expf(p[mi][ni][3]);
                    p[mi][ni][0] = e0; p[mi][ni][1] = e1;
                    p[mi][ni][2] = e2; p[mi][ni][3] = e3;
                    rs[mi][0] += e0 + e1;
                    rs[mi][1] += e2 + e3;
                }

#pragma unroll
            for (int j = 0; j < 8; j++) {
                uint32_t af2[2][4];
#pragma unroll
                for (int mi = 0; mi < 2; mi++) {
                    float t0 = __shfl_sync(0xffffffffu, p[mi][j][0], srcA);
                    float t1 = __shfl_sync(0xffffffffu, p[mi][j][1], srcA);
                    float t2 = __shfl_sync(0xffffffffu, p[mi][j][2], srcA);
                    float t3 = __shfl_sync(0xffffffffu, p[mi][j][3], srcA);
                    float u0 = __shfl_sync(0xffffffffu, p[mi][j][0], srcB);
                    float u1 = __shfl_sync(0xffffffffu, p[mi][j][1], srcB);
                    float u2 = __shfl_sync(0xffffffffu, p[mi][j][2], srcB);
                    float u3 = __shfl_sync(0xffffffffu, p[mi][j][3], srcB);
                    af2[mi][0] = tf32c(sel ? t1 : t0);
                    af2[mi][1] = tf32c(sel ? t3 : t2);
                    af2[mi][2] = tf32c(sel ? u1 : u0);
                    af2[mi][3] = tf32c(sel ? u3 : u2);
                }
                const int cb = h * 64 + j * 8;
#pragma unroll
                for (int nd = 0; nd < 8; nd++) {
                    const int n0 = (nd * 8 + grp) * VS_STRIDE + cb;
                    uint32_t bf[2] = { __float_as_uint(Vc[n0 + qid]),
                                       __float_as_uint(Vc[n0 + qid + 4]) };
                    mma8(oacc[0][nd], af2[0], bf);
                    mma8(oacc[1][nd], af2[1], bf);
                }
            }
        }
        __syncthreads();
    }

    float inv[2][2];
#pragma unroll
    for (int mi = 0; mi < 2; mi++)
#pragma unroll
        for (int r = 0; r < 2; r++) {
            float s = rs[mi][r];
            s += __shfl_xor_sync(0xffffffffu, s, 1);
            s += __shfl_xor_sync(0xffffffffu, s, 2);
            inv[mi][r] = 1.f / s;
        }

    const int b_ = bh >> 4, h_ = bh & 15;
#pragma unroll
    for (int mi = 0; mi < 2; mi++) {
        const int r0 = q0 + w * 32 + mi * 16 + grp;
#pragma unroll
        for (int nd = 0; nd < 8; nd++) {
            const int c = nd * 8 + qid * 2;
            float* d0 = out + ((size_t)b_ * SEQ + r0) * DIM + h_ * HD + c;
            float* d1 = d0 + (size_t)8 * DIM;
            *reinterpret_cast<float2*>(d0) =
                make_float2(tf32f(oacc[mi][nd][0] * inv[mi][0]),
                            tf32f(oacc[mi][nd][1] * inv[mi][0]));
            *reinterpret_cast<float2*>(d1) =
                make_float2(tf32f(oacc[mi][nd][2] * inv[mi][1]),
                            tf32f(oacc[mi][nd][3] * inv[mi][1]));
        }
    }
}

// ---------------- all six weight transposes, one launch, tf32-rounded ------
__global__ __launch_bounds__(256) void transpose_all(
    const float* __restrict__ wq, const float* __restrict__ wk,
    const float* __restrict__ wv, const float* __restrict__ wo,
    const float* __restrict__ w1, const float* __restrict__ w2)
{
    __shared__ float t[32][33];
    int tb = blockIdx.x;
    const float* S; float* D; int R, Cc;
    if (tb < 3072) {
        int m = tb >> 10; tb &= 1023;
        S = (m == 0) ? wq : (m == 1) ? wk : wv;
        D = g_wqkvT + (size_t)m * DIM * DIM;
        R = DIM; Cc = DIM;
    } else if (tb < 4096) {
        tb -= 3072; S = wo; D = g_woT; R = DIM; Cc = DIM;
    } else if (tb < 8192) {
        tb -= 4096; S = w1; D = g_w1T; R = DIM; Cc = FFN;
    } else {
        tb -= 8192; S = w2; D = g_w2T; R = FFN; Cc = DIM;
    }
    const int xt = Cc >> 5;
    const int bx = (tb - (tb / xt) * xt) << 5, by = (tb / xt) << 5;
    const int tx = threadIdx.x;
#pragma unroll
    for (int i = threadIdx.y; i < 32; i += 8)
        t[i][tx] = S[(size_t)(by + i) * Cc + bx + tx];
    __syncthreads();
#pragma unroll
    for (int i = threadIdx.y; i < 32; i += 8)
        D[(size_t)(bx + i) * R + by + tx] = tf32f(t[tx][i]);
}

// ---------------- launcher ----------------
extern "C" void kernel_launch(void* const* d_in, const int* in_sizes, int n_in,
                              void* d_out, int out_size)
{
    const float* x  = (const float*)d_in[0];
    const float* wq = (const float*)d_in[1];
    const float* wk = (const float*)d_in[2];
    const float* wv = (const float*)d_in[3];
    const float* wo = (const float*)d_in[4];
    const float* w1 = (const float*)d_in[5];
    const float* w2 = (const float*)d_in[6];
    float* out = (float*)d_out;

    float *q, *k, *vt, *attn, *x1, *h;
    float *wqkvT, *woT, *w1T, *w2T;
    cudaGetSymbolAddress((void**)&q,     g_q);
    cudaGetSymbolAddress((void**)&k,     g_k);
    cudaGetSymbolAddress((void**)&vt,    g_vt);
    cudaGetSymbolAddress((void**)&attn,  g_attn);
    cudaGetSymbolAddress((void**)&x1,    g_x1);
    cudaGetSymbolAddress((void**)&h,     g_h);
    cudaGetSymbolAddress((void**)&wqkvT, g_wqkvT);
    cudaGetSymbolAddress((void**)&woT,   g_woT);
    cudaGetSymbolAddress((void**)&w1T,   g_w1T);
    cudaGetSymbolAddress((void**)&w2T,   g_w2T);

    cudaFuncSetAttribute(attn_fused,
        cudaFuncAttributeMaxDynamicSharedMemorySize, ATTN_SMEM);
    cudaFuncSetAttribute(gemm256,
        cudaFuncAttributeMaxDynamicSharedMemorySize, GEMM_SMEM);

    // 1: all weight transposes
    transpose_all<<<12288, dim3(32, 8)>>>(wq, wk, wv, wo, w1, w2);

    // 2: fused QKV projection (M=4096, N=3072, K=1024)
    gemm256<<<dim3(12, 32), 256, GEMM_SMEM>>>(
        x, wqkvT, nullptr, nullptr, DIM, DIM, DIM, 0, EPI_QKV);

    // 3: fused attention -> g_attn [token][dim]
    attn_fused<<<dim3(SEQ / 128, BATCH * NH), 128, ATTN_SMEM>>>(
        q, k, vt, attn);

    // 4: WO + residual (M=4096, N=1024, K=1024)
    gemm256<<<dim3(4, 32), 256, GEMM_SMEM>>>(
        attn, woT, x, x1, DIM, DIM, DIM, DIM, EPI_RES);

    // 5: FFN up + relu (M=4096, N=4096, K=1024)
    gemm256<<<dim3(16, 32), 256, GEMM_SMEM>>>(
        x1, w1T, nullptr, h, DIM, DIM, DIM, FFN, EPI_RELU);

    // 6: FFN down + residual -> out (M=4096, N=1024, K=4096)
    gemm256<<<dim3(4, 32), 256, GEMM_SMEM>>>(
        h, w2T, x1, out, FFN, FFN, FFN, DIM, EPI_RES);
}